// round 7
// baseline (speedup 1.0000x reference)
#include <cuda_runtime.h>
#include <cuda_bf16.h>
#include <math.h>

// Problem constants
#define BSZ   16
#define TLEN  512
#define IDIM  8
#define HDIM  256
#define NPAIR 32896              // H*(H+1)/2
#define KSLICE 224               // pairs per CTA (mult of 16)
#define NCTA  148
#define NOWN  128                // owner CTAs (32 outputs each)
#define PPAD  (NCTA*KSLICE)      // 33152 padded pairs
#define ASTRIDE 232              // bf16 elems per A row (116 words -> conflict-free)
#define PSTRIDE 232
#define NOISE_STD 0.05f
#define TAUC 0.2f

#define OFFJ(j) ((j)*HDIM - ((j)*((j)-1))/2)

// Scratch (static device globals: no allocation allowed)
__device__ __nv_bfloat16 g_ws[256 * PPAD];        // packed symmetric weights, bf16
__device__ uchar2        g_jk[PPAD];              // pair -> (j,k)
__device__ float         g_c  [TLEN * HDIM * BSZ];// NOISE_STD*noise + TAU*inp, layout [t][o]
__device__ float         g_x [HDIM * BSZ];        // x, layout [h][b] (o = h*16+b)
__device__ __nv_bfloat16 g_r [HDIM * BSZ];        // tanh(x), bf16, [h][b]
__device__ float         g_part[NCTA * HDIM * BSZ]; // per-CTA partial rec [cta][o]
__device__ __align__(16) unsigned g_arrA[NCTA];   // per-CTA arrival: partials(t) written (t+1)
__device__ __align__(16) unsigned g_arrB[NOWN];   // per-owner arrival: r(t+1) written (t+1)

// ---------------------------------------------------------------- helpers
__device__ __forceinline__ unsigned ld_acq(const unsigned* p) {
    unsigned v;
    asm volatile("ld.acquire.gpu.u32 %0, [%1];" : "=r"(v) : "l"(p));
    return v;
}
__device__ __forceinline__ void st_rel(unsigned* p, unsigned v) {
    asm volatile("st.release.gpu.u32 [%0], %1;" :: "l"(p), "r"(v) : "memory");
}

__device__ __forceinline__ void mma_bf16(float c[4],
        unsigned a0, unsigned a1, unsigned a2, unsigned a3,
        unsigned b0, unsigned b1) {
    asm volatile(
        "mma.sync.aligned.m16n8k16.row.col.f32.bf16.bf16.f32 "
        "{%0,%1,%2,%3}, {%4,%5,%6,%7}, {%8,%9}, {%0,%1,%2,%3};\n"
        : "+f"(c[0]), "+f"(c[1]), "+f"(c[2]), "+f"(c[3])
        : "r"(a0), "r"(a1), "r"(a2), "r"(a3), "r"(b0), "r"(b1));
}

// ---------------------------------------------------------------- prep kernels
__global__ void k_init(const float* __restrict__ x0) {
    int o = blockIdx.x * blockDim.x + threadIdx.x;
    if (o < HDIM * BSZ) {
        int h = o >> 4, b = o & 15;
        float v = x0[b * HDIM + h];
        g_x[o] = v;
        g_r[o] = __float2bfloat16(tanhf(v));
    }
    if (o < NCTA) g_arrA[o] = 0u;
    if (o < NOWN) g_arrB[o] = 0u;
}

__global__ void k_jk() {
    int p = blockIdx.x * blockDim.x + threadIdx.x;
    if (p >= PPAD) return;
    if (p >= NPAIR) { g_jk[p] = make_uchar2(0, 0); return; }
    double H2 = 2.0 * HDIM + 1.0;
    int j = (int)((H2 - sqrt(H2 * H2 - 8.0 * (double)p)) * 0.5);
    if (j < 0) j = 0;
    if (j > HDIM - 1) j = HDIM - 1;
    while (j + 1 <= HDIM - 1 && OFFJ(j + 1) <= p) j++;
    while (j > 0 && OFFJ(j) > p) j--;
    int k = j + (p - OFFJ(j));
    g_jk[p] = make_uchar2((unsigned char)j, (unsigned char)k);
}

// zero the padded tail of each weight row (pairs NPAIR..PPAD-1)
__global__ void k_pad() {
    int idx = blockIdx.x * blockDim.x + threadIdx.x;
    const int padw = PPAD - NPAIR;            // 256
    int i = idx / padw, p = NPAIR + idx % padw;
    if (i < 256) g_ws[i * PPAD + p] = __float2bfloat16(0.f);
}

// symmetrize via 32x32 SMEM tile transpose: both reads coalesced.
// grid = (36 tile-pairs, 256 i), block = 256
__global__ void k_ws(const float* __restrict__ w_hh) {
    __shared__ float tA[32][33];
    __shared__ float tB[32][33];
    const int i = blockIdx.y;
    int tp = blockIdx.x;                      // 0..35 -> (jt<=kt) among 8x8
    int jt = 0, kt = 0, acc = 0;
#pragma unroll
    for (int r = 0; r < 8; r++) {
        int cnt = 8 - r;
        if (tp < acc + cnt) { jt = r; kt = r + (tp - acc); break; }
        acc += cnt;
    }
    const int lr = threadIdx.x >> 5, lc = threadIdx.x & 31;
    const float* Wi = w_hh + i * 65536;
#pragma unroll
    for (int rr = 0; rr < 32; rr += 8) {
        tA[rr + lr][lc] = Wi[(jt * 32 + rr + lr) * 256 + kt * 32 + lc];
        tB[rr + lr][lc] = Wi[(kt * 32 + rr + lr) * 256 + jt * 32 + lc];
    }
    __syncthreads();
#pragma unroll
    for (int q = 0; q < 4; q++) {
        int j = q * 8 + lr, k = lc;
        int J = jt * 32 + j, K = kt * 32 + k;
        if (J <= K) {
            float v = (J == K) ? tA[j][k] : tA[j][k] + tB[k][j];
            int p = OFFJ(J) + (K - J);
            g_ws[i * PPAD + p] = __float2bfloat16(v);
        }
    }
}

// c[t][o] = NOISE_STD * noise[t,b,h] + TAU * (u @ w_in + b_in)[t,b,h]
__global__ void k_pre(const float* __restrict__ u,
                      const float* __restrict__ w_in_w,
                      const float* __restrict__ w_in_b,
                      const float* __restrict__ noise) {
    int idx = blockIdx.x * blockDim.x + threadIdx.x;
    if (idx >= TLEN * HDIM * BSZ) return;
    int t = idx / (HDIM * BSZ);
    int r = idx - t * (HDIM * BSZ);
    int h = r >> 4, b = r & 15;
    const float* up = u + (b * TLEN + t) * IDIM;
    float acc = w_in_b[h];
#pragma unroll
    for (int i = 0; i < IDIM; i++) acc += up[i] * w_in_w[h * IDIM + i];
    float n = noise[t * (BSZ * HDIM) + b * HDIM + h];
    g_c[idx] = NOISE_STD * n + TAUC * acc;
}

// ---------------------------------------------------------------- main persistent kernel
#define SMEM_A   0
#define SMEM_P   (256 * ASTRIDE * 2)                 // 118784
#define SMEM_R   (SMEM_P + 16 * PSTRIDE * 2)         // 126208
#define SMEM_JK  (SMEM_R + HDIM * BSZ * 2)           // 134400
#define SMEM_RED (SMEM_JK + KSLICE * 2)              // 134848
#define SMEM_TOT (SMEM_RED + 8 * 32 * 4)             // 135872

extern __shared__ char smem_raw[];

__global__ void __launch_bounds__(256, 1)
k_main(float* __restrict__ traj, float* __restrict__ xlast) {
    __nv_bfloat16* A_s = (__nv_bfloat16*)(smem_raw + SMEM_A);   // [256][ASTRIDE]
    __nv_bfloat16* P_s = (__nv_bfloat16*)(smem_raw + SMEM_P);   // [16][PSTRIDE]
    __nv_bfloat16* r_s = (__nv_bfloat16*)(smem_raw + SMEM_R);   // [h][b]
    uchar2*        jk_s = (uchar2*)(smem_raw + SMEM_JK);        // [KSLICE]
    float*         red_s = (float*)(smem_raw + SMEM_RED);       // [8][32]

    const int tid  = threadIdx.x;
    const int cta  = blockIdx.x;
    const int lane = tid & 31;
    const int warp = tid >> 5;
    const int g    = lane >> 2;     // groupID
    const int tq   = lane & 3;      // threadID_in_group

    // Load this CTA's A slice (packed symmetric weights) into SMEM — once.
    const int c0 = cta * KSLICE;
    for (int idx = tid; idx < 256 * KSLICE; idx += 256) {
        int i = idx / KSLICE, kk = idx - i * KSLICE;
        A_s[i * ASTRIDE + kk] = g_ws[i * PPAD + c0 + kk];
    }
    for (int idx = tid; idx < KSLICE; idx += 256) jk_s[idx] = g_jk[c0 + idx];
    __syncthreads();

    const unsigned* As32 = (const unsigned*)A_s;   // stride 116 words per row
    const unsigned* Ps32 = (const unsigned*)P_s;

    const bool owner = (cta < NOWN);
    const int o_own = cta * 32 + lane;             // valid when owner && warp==0
    float xreg = 0.f;
    if (owner && warp == 0) xreg = g_x[o_own];

    for (int t = 0; t < TLEN; t++) {
        // ---- fused: wait for r(t) (warp polls its 16 contiguous owner flags
        //      in parallel) then load exactly this warp's 1KB chunk of r.
        if (t > 0) {
            unsigned done = (lane < 16) ? 0u : 1u;
            const unsigned* f = &g_arrB[warp * 16 + (lane & 15)];
            do {
                if (!done) done = (ld_acq(f) >= (unsigned)t) ? 1u : 0u;
            } while (!__all_sync(0xffffffffu, done));
            const uint4* src = (const uint4*)g_r;   // 512 x uint4 total
            uint4* dst = (uint4*)r_s;
            int i0 = warp * 64 + lane * 2;
            dst[i0]     = __ldcg(src + i0);
            dst[i0 + 1] = __ldcg(src + i0 + 1);
        } else {
            const uint4* src = (const uint4*)g_r;
            uint4* dst = (uint4*)r_s;
            for (int i2 = tid; i2 < 512; i2 += 256) dst[i2] = __ldcg(src + i2);
        }
        __syncthreads();

        // ---- prefetch the per-step drive term early
        float cpre = 0.f;
        if (owner && warp == 0) cpre = g_c[t * (HDIM * BSZ) + o_own];

        // ---- build outer-product B tile: P_s[b][p] = r[b,j(p)] * r[b,k(p)]
        if (tid < KSLICE) {
            uchar2 jk = jk_s[tid];
            const __nv_bfloat16* rj = r_s + ((int)jk.x) * BSZ;
            const __nv_bfloat16* rk = r_s + ((int)jk.y) * BSZ;
#pragma unroll
            for (int n = 0; n < BSZ; n++) {
                float v = __bfloat162float(rj[n]) * __bfloat162float(rk[n]);
                P_s[n * PSTRIDE + tid] = __float2bfloat16(v);
            }
        }
        __syncthreads();

        // ---- MMA: D[256x16] += A[256 x KSLICE] * P[KSLICE x 16]
        float acc[2][2][4];
#pragma unroll
        for (int m2 = 0; m2 < 2; m2++)
#pragma unroll
            for (int nt = 0; nt < 2; nt++)
#pragma unroll
                for (int q = 0; q < 4; q++) acc[m2][nt][q] = 0.f;

#pragma unroll 2
        for (int kt = 0; kt < KSLICE / 16; kt++) {
            const int kw = kt * 8 + tq;   // word column base
            unsigned b0[2], b1[2];
#pragma unroll
            for (int nt = 0; nt < 2; nt++) {
                int n = nt * 8 + g;
                b0[nt] = Ps32[n * (PSTRIDE / 2) + kw];
                b1[nt] = Ps32[n * (PSTRIDE / 2) + kw + 4];
            }
#pragma unroll
            for (int m2 = 0; m2 < 2; m2++) {
                int mrow = (warp * 2 + m2) * 16 + g;
                unsigned a0 = As32[mrow       * (ASTRIDE / 2) + kw];
                unsigned a1 = As32[(mrow + 8) * (ASTRIDE / 2) + kw];
                unsigned a2 = As32[mrow       * (ASTRIDE / 2) + kw + 4];
                unsigned a3 = As32[(mrow + 8) * (ASTRIDE / 2) + kw + 4];
#pragma unroll
                for (int nt = 0; nt < 2; nt++)
                    mma_bf16(acc[m2][nt], a0, a1, a2, a3, b0[nt], b1[nt]);
            }
        }

        // ---- write partial rec for this CTA (coalesced, o = i*16 + b)
        {
            float* pc = g_part + cta * (HDIM * BSZ);
#pragma unroll
            for (int m2 = 0; m2 < 2; m2++) {
                int ibase = (warp * 2 + m2) * 16 + g;
#pragma unroll
                for (int nt = 0; nt < 2; nt++) {
                    int bb = nt * 8 + tq * 2;
                    *(float2*)(pc + ibase * 16 + bb)       = make_float2(acc[m2][nt][0], acc[m2][nt][1]);
                    *(float2*)(pc + (ibase + 8) * 16 + bb) = make_float2(acc[m2][nt][2], acc[m2][nt][3]);
                }
            }
        }
        __syncthreads();                       // all partial stores issued
        if (tid == 0) st_rel(&g_arrA[cta], (unsigned)(t + 1));  // release covers prior writes

        // ---- phase B (owners only): fused wait+reduce.
        //      warp w owns contiguous producer range [19w, min(148,19w+19))
        if (owner) {
            const int start = warp * 19;
            const int cnt = min(NCTA - start, 19);          // 19, warp7 -> 15
            {
                unsigned done = (lane < cnt) ? 0u : 1u;
                const unsigned* f = &g_arrA[start + (lane < cnt ? lane : 0)];
                do {
                    if (!done) done = (ld_acq(f) >= (unsigned)(t + 1)) ? 1u : 0u;
                } while (!__all_sync(0xffffffffu, done));
            }
            const float* pp = g_part + cta * 32 + lane;
            float s0 = 0.f, s1 = 0.f;
#pragma unroll
            for (int it = 0; it < 19; it++) {
                if (it < cnt) {
                    float v = __ldcg(pp + (start + it) * (HDIM * BSZ));
                    if (it & 1) s1 += v; else s0 += v;
                }
            }
            red_s[warp * 32 + lane] = s0 + s1;
            __syncthreads();

            if (warp == 0) {
                float rec = 0.f;
#pragma unroll
                for (int w = 0; w < 8; w++) rec += red_s[w * 32 + lane];
                float xn = 0.8f * xreg + TAUC * rec + cpre;
                xreg = xn;
                g_r[o_own] = __float2bfloat16(tanhf(xn));
                int h = o_own >> 4, b = o_own & 15;
                traj[b * (TLEN * HDIM) + t * HDIM + h] = xn;
                if (t == TLEN - 1) xlast[b * HDIM + h] = xn;
                __syncwarp();
                if (lane == 0) st_rel(&g_arrB[cta], (unsigned)(t + 1));
            }
        }
    }
}

// ---------------------------------------------------------------- output projection
__global__ void k_out(const float* __restrict__ w_out_w,
                      const float* __restrict__ w_out_b,
                      const float* __restrict__ traj,
                      float* __restrict__ outp) {
    __shared__ float s_t[HDIM];
    int bt = blockIdx.x;                 // b*TLEN + t
    int tid = threadIdx.x;
    s_t[tid] = tanhf(traj[bt * HDIM + tid]);
    __syncthreads();
    int warp = tid >> 5, lane = tid & 31;
    float acc = 0.f;
#pragma unroll
    for (int q = 0; q < 8; q++)
        acc += s_t[lane + q * 32] * w_out_w[warp * HDIM + lane + q * 32];
#pragma unroll
    for (int off = 16; off; off >>= 1)
        acc += __shfl_xor_sync(0xffffffffu, acc, off);
    if (lane == 0) outp[bt * IDIM + warp] = acc + w_out_b[warp];
}

// ---------------------------------------------------------------- launch
extern "C" void kernel_launch(void* const* d_in, const int* in_sizes, int n_in,
                              void* d_out, int out_size) {
    const float* u       = (const float*)d_in[0];
    const float* x0      = (const float*)d_in[1];
    const float* noise   = (const float*)d_in[2];
    const float* w_hh    = (const float*)d_in[3];
    const float* w_in_w  = (const float*)d_in[4];
    const float* w_in_b  = (const float*)d_in[5];
    const float* w_out_w = (const float*)d_in[6];
    const float* w_out_b = (const float*)d_in[7];

    float* outp  = (float*)d_out;                       // [B,T,I]
    float* xlast = outp + BSZ * TLEN * IDIM;            // [B,H]
    float* traj  = xlast + BSZ * HDIM;                  // [B,T,H]

    cudaFuncSetAttribute(k_main, cudaFuncAttributeMaxDynamicSharedMemorySize, SMEM_TOT);

    k_init<<<(HDIM * BSZ + 255) / 256, 256>>>(x0);
    k_jk<<<(PPAD + 255) / 256, 256>>>();
    k_pad<<<(256 * (PPAD - NPAIR) + 255) / 256, 256>>>();
    dim3 gw(36, 256);
    k_ws<<<gw, 256>>>(w_hh);
    k_pre<<<(TLEN * HDIM * BSZ + 255) / 256, 256>>>(u, w_in_w, w_in_b, noise);
    k_main<<<NCTA, 256, SMEM_TOT>>>(traj, xlast);
    k_out<<<BSZ * TLEN, 256>>>(w_out_w, w_out_b, traj, outp);
}

// round 9
// speedup vs baseline: 3.1574x; 3.1574x over previous
#include <cuda_runtime.h>
#include <cuda_bf16.h>
#include <math.h>

// Problem constants
#define BSZ   16
#define TLEN  512
#define IDIM  8
#define HDIM  256
#define NPAIR 32896              // H*(H+1)/2
#define KSLICE 224               // pairs per CTA (mult of 16)
#define NCTA  148
#define NOWN  128                // owner CTAs (32 outputs each)
#define AGG   (NCTA-1)           // dedicated aggregator CTA (non-owner)
#define PPAD  (NCTA*KSLICE)      // 33152 padded pairs
#define ASTRIDE 232              // bf16 elems per A row (116 words -> conflict-free)
#define PSTRIDE 232
#define NOISE_STD 0.05f
#define TAUC 0.2f

#define OFFJ(j) ((j)*HDIM - ((j)*((j)-1))/2)

// Scratch (static device globals: no allocation allowed)
__device__ __nv_bfloat16 g_ws[256 * PPAD];        // packed symmetric weights, bf16
__device__ uchar2        g_jk[PPAD];              // pair -> (j,k)
__device__ float         g_c  [TLEN * HDIM * BSZ];// NOISE_STD*noise + TAU*inp, layout [t][o]
__device__ float         g_x [HDIM * BSZ];        // x, layout [h][b] (o = h*16+b)
__device__ __nv_bfloat16 g_r [HDIM * BSZ];        // tanh(x), bf16, [h][b]
__device__ float         g_part[NCTA * HDIM * BSZ]; // per-CTA partial rec [cta][o]
__device__ __align__(16) unsigned g_arrA[NCTA];   // per-CTA arrival: partials(t) written (t+1)
__device__ __align__(16) unsigned g_arrB[NOWN];   // per-owner arrival: r(t+1) written (t+1)
__device__ unsigned      g_epochA;                // all partials ready
__device__ unsigned      g_epochB;                // r ready

// ---------------------------------------------------------------- helpers
__device__ __forceinline__ unsigned ld_acq(const unsigned* p) {
    unsigned v;
    asm volatile("ld.acquire.gpu.u32 %0, [%1];" : "=r"(v) : "l"(p));
    return v;
}
__device__ __forceinline__ void st_rel(unsigned* p, unsigned v) {
    asm volatile("st.release.gpu.u32 [%0], %1;" :: "l"(p), "r"(v) : "memory");
}
__device__ __forceinline__ uint4 ld_rlx_v4(const unsigned* p) {
    uint4 v;
    asm volatile("ld.relaxed.gpu.v4.u32 {%0,%1,%2,%3}, [%4];"
                 : "=r"(v.x), "=r"(v.y), "=r"(v.z), "=r"(v.w) : "l"(p));
    return v;
}
__device__ __forceinline__ void fence_acqrel() {
    asm volatile("fence.acq_rel.gpu;" ::: "memory");
}

// the ONLY wide poller on the chip: aggregator warp. nflags % 4 == 0.
__device__ __forceinline__ void aggregate(const unsigned* flags, int nflags,
                                          unsigned target, unsigned* epoch, int lane) {
    const int nl = nflags >> 2;
    for (;;) {
        unsigned ok = 1;
        if (lane < nl) {
            uint4 v = ld_rlx_v4(flags + lane * 4);
            ok = (v.x >= target) & (v.y >= target) & (v.z >= target) & (v.w >= target);
        }
        if (__all_sync(0xffffffffu, ok)) break;
    }
    fence_acqrel();
    if (lane == 0) st_rel(epoch, target);
}

__device__ __forceinline__ void mma_bf16(float c[4],
        unsigned a0, unsigned a1, unsigned a2, unsigned a3,
        unsigned b0, unsigned b1) {
    asm volatile(
        "mma.sync.aligned.m16n8k16.row.col.f32.bf16.bf16.f32 "
        "{%0,%1,%2,%3}, {%4,%5,%6,%7}, {%8,%9}, {%0,%1,%2,%3};\n"
        : "+f"(c[0]), "+f"(c[1]), "+f"(c[2]), "+f"(c[3])
        : "r"(a0), "r"(a1), "r"(a2), "r"(a3), "r"(b0), "r"(b1));
}

// ---------------------------------------------------------------- prep kernels
__global__ void k_init(const float* __restrict__ x0) {
    int o = blockIdx.x * blockDim.x + threadIdx.x;
    if (o < HDIM * BSZ) {
        int h = o >> 4, b = o & 15;
        float v = x0[b * HDIM + h];
        g_x[o] = v;
        g_r[o] = __float2bfloat16(tanhf(v));
    }
    if (o < NCTA) g_arrA[o] = 0u;
    if (o < NOWN) g_arrB[o] = 0u;
    if (o == 0) { g_epochA = 0u; g_epochB = 0u; }
}

__global__ void k_jk() {
    int p = blockIdx.x * blockDim.x + threadIdx.x;
    if (p >= PPAD) return;
    if (p >= NPAIR) { g_jk[p] = make_uchar2(0, 0); return; }
    double H2 = 2.0 * HDIM + 1.0;
    int j = (int)((H2 - sqrt(H2 * H2 - 8.0 * (double)p)) * 0.5);
    if (j < 0) j = 0;
    if (j > HDIM - 1) j = HDIM - 1;
    while (j + 1 <= HDIM - 1 && OFFJ(j + 1) <= p) j++;
    while (j > 0 && OFFJ(j) > p) j--;
    int k = j + (p - OFFJ(j));
    g_jk[p] = make_uchar2((unsigned char)j, (unsigned char)k);
}

// zero the padded tail of each weight row (pairs NPAIR..PPAD-1)
__global__ void k_pad() {
    int idx = blockIdx.x * blockDim.x + threadIdx.x;
    const int padw = PPAD - NPAIR;            // 256
    int i = idx / padw, p = NPAIR + idx % padw;
    if (i < 256) g_ws[i * PPAD + p] = __float2bfloat16(0.f);
}

// symmetrize via 32x32 SMEM tile transpose: both reads coalesced.
// grid = (36 tile-pairs, 256 i), block = 256
__global__ void k_ws(const float* __restrict__ w_hh) {
    __shared__ float tA[32][33];
    __shared__ float tB[32][33];
    const int i = blockIdx.y;
    int tp = blockIdx.x;                      // 0..35 -> (jt<=kt) among 8x8
    int jt = 0, kt = 0, acc = 0;
#pragma unroll
    for (int r = 0; r < 8; r++) {
        int cnt = 8 - r;
        if (tp < acc + cnt) { jt = r; kt = r + (tp - acc); break; }
        acc += cnt;
    }
    const int lr = threadIdx.x >> 5, lc = threadIdx.x & 31;
    const float* Wi = w_hh + i * 65536;
#pragma unroll
    for (int rr = 0; rr < 32; rr += 8) {
        tA[rr + lr][lc] = Wi[(jt * 32 + rr + lr) * 256 + kt * 32 + lc];
        tB[rr + lr][lc] = Wi[(kt * 32 + rr + lr) * 256 + jt * 32 + lc];
    }
    __syncthreads();
#pragma unroll
    for (int q = 0; q < 4; q++) {
        int j = q * 8 + lr, k = lc;
        int J = jt * 32 + j, K = kt * 32 + k;
        if (J <= K) {
            float v = (J == K) ? tA[j][k] : tA[j][k] + tB[k][j];
            int p = OFFJ(J) + (K - J);
            g_ws[i * PPAD + p] = __float2bfloat16(v);
        }
    }
}

// c[t][o] = NOISE_STD * noise[t,b,h] + TAU * (u @ w_in + b_in)[t,b,h]
__global__ void k_pre(const float* __restrict__ u,
                      const float* __restrict__ w_in_w,
                      const float* __restrict__ w_in_b,
                      const float* __restrict__ noise) {
    int idx = blockIdx.x * blockDim.x + threadIdx.x;
    if (idx >= TLEN * HDIM * BSZ) return;
    int t = idx / (HDIM * BSZ);
    int r = idx - t * (HDIM * BSZ);
    int h = r >> 4, b = r & 15;
    const float* up = u + (b * TLEN + t) * IDIM;
    float acc = w_in_b[h];
#pragma unroll
    for (int i = 0; i < IDIM; i++) acc += up[i] * w_in_w[h * IDIM + i];
    float n = noise[t * (BSZ * HDIM) + b * HDIM + h];
    g_c[idx] = NOISE_STD * n + TAUC * acc;
}

// ---------------------------------------------------------------- main persistent kernel
#define SMEM_A   0
#define SMEM_P   (256 * ASTRIDE * 2)                 // 118784
#define SMEM_R   (SMEM_P + 16 * PSTRIDE * 2)         // 126208
#define SMEM_JK  (SMEM_R + HDIM * BSZ * 2)           // 134400
#define SMEM_RED (SMEM_JK + KSLICE * 2)              // 134848
#define SMEM_TOT (SMEM_RED + 8 * 32 * 4)             // 135872

extern __shared__ char smem_raw[];

__global__ void __launch_bounds__(256, 1)
k_main(float* __restrict__ traj, float* __restrict__ xlast) {
    __nv_bfloat16* A_s = (__nv_bfloat16*)(smem_raw + SMEM_A);   // [256][ASTRIDE]
    __nv_bfloat16* P_s = (__nv_bfloat16*)(smem_raw + SMEM_P);   // [16][PSTRIDE]
    __nv_bfloat16* r_s = (__nv_bfloat16*)(smem_raw + SMEM_R);   // [h][b]
    uchar2*        jk_s = (uchar2*)(smem_raw + SMEM_JK);        // [KSLICE]
    float*         red_s = (float*)(smem_raw + SMEM_RED);       // [8][32]

    const int tid  = threadIdx.x;
    const int cta  = blockIdx.x;
    const int lane = tid & 31;
    const int warp = tid >> 5;
    const int g    = lane >> 2;     // groupID
    const int tq   = lane & 3;      // threadID_in_group

    // Load this CTA's A slice (packed symmetric weights) into SMEM — once.
    const int c0 = cta * KSLICE;
    for (int idx = tid; idx < 256 * KSLICE; idx += 256) {
        int i = idx / KSLICE, kk = idx - i * KSLICE;
        A_s[i * ASTRIDE + kk] = g_ws[i * PPAD + c0 + kk];
    }
    for (int idx = tid; idx < KSLICE; idx += 256) jk_s[idx] = g_jk[c0 + idx];
    __syncthreads();

    const unsigned* As32 = (const unsigned*)A_s;   // stride 116 words per row
    const unsigned* Ps32 = (const unsigned*)P_s;

    const bool owner = (cta < NOWN);
    const int o_own = cta * 32 + lane;             // valid when owner && warp==0
    float xreg = 0.f;
    if (owner && warp == 0) xreg = g_x[o_own];

    for (int t = 0; t < TLEN; t++) {
        // ---- wait until r(t) is published: ONE thread polls the epoch word
        if (t > 0) {
            if (tid == 0) { while (ld_acq(&g_epochB) < (unsigned)t) { } }
            __syncthreads();
        }

        // ---- prefetch the per-step drive term early
        float cpre = 0.f;
        if (owner && warp == 0) cpre = g_c[t * (HDIM * BSZ) + o_own];

        // ---- load current r (bf16 [h][b]) into SMEM, bypass L1
        {
            const uint4* src = (const uint4*)g_r;   // 512 x uint4
            uint4* dst = (uint4*)r_s;
            for (int i2 = tid; i2 < 512; i2 += 256) dst[i2] = __ldcg(src + i2);
        }
        __syncthreads();

        // ---- build outer-product B tile: P_s[b][p] = r[b,j(p)] * r[b,k(p)]
        if (tid < KSLICE) {
            uchar2 jk = jk_s[tid];
            const __nv_bfloat16* rj = r_s + ((int)jk.x) * BSZ;
            const __nv_bfloat16* rk = r_s + ((int)jk.y) * BSZ;
#pragma unroll
            for (int n = 0; n < BSZ; n++) {
                float v = __bfloat162float(rj[n]) * __bfloat162float(rk[n]);
                P_s[n * PSTRIDE + tid] = __float2bfloat16(v);
            }
        }
        __syncthreads();

        // ---- MMA: D[256x16] += A[256 x KSLICE] * P[KSLICE x 16]
        float acc[2][2][4];
#pragma unroll
        for (int m2 = 0; m2 < 2; m2++)
#pragma unroll
            for (int nt = 0; nt < 2; nt++)
#pragma unroll
                for (int q = 0; q < 4; q++) acc[m2][nt][q] = 0.f;

#pragma unroll 2
        for (int kt = 0; kt < KSLICE / 16; kt++) {
            const int kw = kt * 8 + tq;   // word column base
            unsigned b0[2], b1[2];
#pragma unroll
            for (int nt = 0; nt < 2; nt++) {
                int n = nt * 8 + g;
                b0[nt] = Ps32[n * (PSTRIDE / 2) + kw];
                b1[nt] = Ps32[n * (PSTRIDE / 2) + kw + 4];
            }
#pragma unroll
            for (int m2 = 0; m2 < 2; m2++) {
                int mrow = (warp * 2 + m2) * 16 + g;
                unsigned a0 = As32[mrow       * (ASTRIDE / 2) + kw];
                unsigned a1 = As32[(mrow + 8) * (ASTRIDE / 2) + kw];
                unsigned a2 = As32[mrow       * (ASTRIDE / 2) + kw + 4];
                unsigned a3 = As32[(mrow + 8) * (ASTRIDE / 2) + kw + 4];
#pragma unroll
                for (int nt = 0; nt < 2; nt++)
                    mma_bf16(acc[m2][nt], a0, a1, a2, a3, b0[nt], b1[nt]);
            }
        }

        // ---- write partial rec for this CTA (coalesced, o = i*16 + b)
        {
            float* pc = g_part + cta * (HDIM * BSZ);
#pragma unroll
            for (int m2 = 0; m2 < 2; m2++) {
                int ibase = (warp * 2 + m2) * 16 + g;
#pragma unroll
                for (int nt = 0; nt < 2; nt++) {
                    int bb = nt * 8 + tq * 2;
                    *(float2*)(pc + ibase * 16 + bb)       = make_float2(acc[m2][nt][0], acc[m2][nt][1]);
                    *(float2*)(pc + (ibase + 8) * 16 + bb) = make_float2(acc[m2][nt][2], acc[m2][nt][3]);
                }
            }
        }
        __syncthreads();                       // all partial stores issued
        if (tid == 0) st_rel(&g_arrA[cta], (unsigned)(t + 1));

        // ---- aggregator CTA: the only wide poller on the chip
        if (cta == AGG) {
            if (warp == 0) {
                aggregate(g_arrA, NCTA, (unsigned)(t + 1), &g_epochA, lane);
                if (t < TLEN - 1)
                    aggregate(g_arrB, NOWN, (unsigned)(t + 1), &g_epochB, lane);
            }
        }

        // ---- phase B (owners only): single-thread epoch wait, then reduce+update
        if (owner) {
            if (tid == 0) { while (ld_acq(&g_epochA) < (unsigned)(t + 1)) { } }
            __syncthreads();

            const float* pp = g_part + cta * 32 + lane;
            float s0 = 0.f, s1 = 0.f;
#pragma unroll
            for (int it = 0; it < 19; it++) {
                int c = warp + it * 8;
                if (c < NCTA) {
                    float v = __ldcg(pp + c * (HDIM * BSZ));
                    if (it & 1) s1 += v; else s0 += v;
                }
            }
            red_s[warp * 32 + lane] = s0 + s1;
            __syncthreads();

            if (warp == 0) {
                float rec = 0.f;
#pragma unroll
                for (int w = 0; w < 8; w++) rec += red_s[w * 32 + lane];
                float xn = 0.8f * xreg + TAUC * rec + cpre;
                xreg = xn;
                g_r[o_own] = __float2bfloat16(tanhf(xn));
                int h = o_own >> 4, b = o_own & 15;
                traj[b * (TLEN * HDIM) + t * HDIM + h] = xn;
                if (t == TLEN - 1) xlast[b * HDIM + h] = xn;
                __syncwarp();
                if (lane == 0) st_rel(&g_arrB[cta], (unsigned)(t + 1));
            }
        }
    }
}

// ---------------------------------------------------------------- output projection
__global__ void k_out(const float* __restrict__ w_out_w,
                      const float* __restrict__ w_out_b,
                      const float* __restrict__ traj,
                      float* __restrict__ outp) {
    __shared__ float s_t[HDIM];
    int bt = blockIdx.x;                 // b*TLEN + t
    int tid = threadIdx.x;
    s_t[tid] = tanhf(traj[bt * HDIM + tid]);
    __syncthreads();
    int warp = tid >> 5, lane = tid & 31;
    float acc = 0.f;
#pragma unroll
    for (int q = 0; q < 8; q++)
        acc += s_t[lane + q * 32] * w_out_w[warp * HDIM + lane + q * 32];
#pragma unroll
    for (int off = 16; off; off >>= 1)
        acc += __shfl_xor_sync(0xffffffffu, acc, off);
    if (lane == 0) outp[bt * IDIM + warp] = acc + w_out_b[warp];
}

// ---------------------------------------------------------------- launch
extern "C" void kernel_launch(void* const* d_in, const int* in_sizes, int n_in,
                              void* d_out, int out_size) {
    const float* u       = (const float*)d_in[0];
    const float* x0      = (const float*)d_in[1];
    const float* noise   = (const float*)d_in[2];
    const float* w_hh    = (const float*)d_in[3];
    const float* w_in_w  = (const float*)d_in[4];
    const float* w_in_b  = (const float*)d_in[5];
    const float* w_out_w = (const float*)d_in[6];
    const float* w_out_b = (const float*)d_in[7];

    float* outp  = (float*)d_out;                       // [B,T,I]
    float* xlast = outp + BSZ * TLEN * IDIM;            // [B,H]
    float* traj  = xlast + BSZ * HDIM;                  // [B,T,H]

    cudaFuncSetAttribute(k_main, cudaFuncAttributeMaxDynamicSharedMemorySize, SMEM_TOT);

    k_init<<<(HDIM * BSZ + 255) / 256, 256>>>(x0);
    k_jk<<<(PPAD + 255) / 256, 256>>>();
    k_pad<<<(256 * (PPAD - NPAIR) + 255) / 256, 256>>>();
    dim3 gw(36, 256);
    k_ws<<<gw, 256>>>(w_hh);
    k_pre<<<(TLEN * HDIM * BSZ + 255) / 256, 256>>>(u, w_in_w, w_in_b, noise);
    k_main<<<NCTA, 256, SMEM_TOT>>>(traj, xlast);
    k_out<<<BSZ * TLEN, 256>>>(w_out_w, w_out_b, traj, outp);
}